// round 2
// baseline (speedup 1.0000x reference)
#include <cuda_runtime.h>
#include <cstddef>

// Problem constants
#define E_EDGES 100000
#define N_NODES 25000
#define HID 512
#define NG 2048
#define FN 133
#define FE 14
#define KEI 147    // F_NODE + F_EDGE
#define KE2N 645   // F_NODE + HIDDEN

// ---------------------------------------------------------------------------
// Scratch (device globals; allocation-free per harness rules)
// ---------------------------------------------------------------------------
__device__ float g_h0[(size_t)E_EDGES * HID];     // 204.8 MB
__device__ float g_hA[(size_t)E_EDGES * HID];     // 204.8 MB
__device__ float g_hB[(size_t)E_EDGES * HID];     // 204.8 MB
__device__ float g_aA[(size_t)N_NODES * HID];     // 51.2 MB
__device__ float g_aB[(size_t)N_NODES * HID];     // 51.2 MB
__device__ float g_pool[(size_t)NG * HID];        // 4 MB

// Vectorized fp32 global reduction (sm_90+)
__device__ __forceinline__ void red_add_v4(float* addr, float x, float y, float z, float w) {
    asm volatile("red.global.add.v4.f32 [%0], {%1,%2,%3,%4};"
                 :: "l"(addr), "f"(x), "f"(y), "f"(z), "f"(w) : "memory");
}

// ---------------------------------------------------------------------------
// Zero fill
// ---------------------------------------------------------------------------
__global__ void zero_kernel(float4* __restrict__ p, int n4) {
    int i = blockIdx.x * blockDim.x + threadIdx.x;
    int stride = gridDim.x * blockDim.x;
    for (; i < n4; i += stride) p[i] = make_float4(0.f, 0.f, 0.f, 0.f);
}

// ---------------------------------------------------------------------------
// Edge init: h0[e] = relu([x[row[e]], edge_attr[e]] @ W_ei + b_ei)
// epilogue also scatters: aA[col[e]] += h0[e]  (a for layer 0)
// M = E_EDGES, K = 147 (padded to 152), N = 512.
// edge_index is int32 [2][E]: row = ei[e], col = ei[E + e].
// ---------------------------------------------------------------------------
__global__ __launch_bounds__(256, 2)
void edge_init_kernel(const float* __restrict__ x, const float* __restrict__ ea,
                      const float* __restrict__ W, const float* __restrict__ bias,
                      const int* __restrict__ ei)
{
    __shared__ float As[8][132];
    __shared__ float Bs[8][128];
    const int tid = threadIdx.x;
    const int tx = tid & 15, ty = tid >> 4;
    const int bm = blockIdx.y * 128;
    const int bn = blockIdx.x * 128;

    const int arow = tid >> 1;
    const int ac4  = (tid & 1) * 4;
    const int am   = bm + arow;
    const bool aValid = (am < E_EDGES);
    const int r = aValid ? ei[am] : 0;               // row[am]

    const int brow = tid >> 5;
    const int bc4  = (tid & 31) * 4;

    float acc[8][8];
    #pragma unroll
    for (int i = 0; i < 8; i++)
        #pragma unroll
        for (int j = 0; j < 8; j++) acc[i][j] = 0.f;

    for (int k0 = 0; k0 < 152; k0 += 8) {
        // A tile (gathered concat), scalar loads with k guard
        #pragma unroll
        for (int i = 0; i < 4; i++) {
            int k = k0 + ac4 + i;
            float v = 0.f;
            if (aValid && k < KEI) {
                v = (k < FN) ? x[(size_t)r * FN + k]
                             : ea[(size_t)am * FE + (k - FN)];
            }
            As[ac4 + i][arow] = v;
        }
        // B tile
        int kRow = k0 + brow;
        float4 bv = make_float4(0.f, 0.f, 0.f, 0.f);
        if (kRow < KEI) bv = *(const float4*)(W + (size_t)kRow * HID + bn + bc4);
        *(float4*)&Bs[brow][bc4] = bv;
        __syncthreads();

        #pragma unroll
        for (int kk = 0; kk < 8; kk++) {
            float ar[8], br[8];
            #pragma unroll
            for (int i = 0; i < 8; i++) ar[i] = As[kk][ty * 8 + i];
            #pragma unroll
            for (int j = 0; j < 8; j++) br[j] = Bs[kk][tx * 8 + j];
            #pragma unroll
            for (int i = 0; i < 8; i++)
                #pragma unroll
                for (int j = 0; j < 8; j++) acc[i][j] += ar[i] * br[j];
        }
        __syncthreads();
    }

    const int n0 = bn + tx * 8;
    float bres[8];
    #pragma unroll
    for (int j = 0; j < 8; j++) bres[j] = bias[n0 + j];

    #pragma unroll
    for (int i = 0; i < 8; i++) {
        int m = bm + ty * 8 + i;
        if (m < E_EDGES) {
            float v[8];
            #pragma unroll
            for (int j = 0; j < 8; j++) {
                float t = acc[i][j] + bres[j];
                v[j] = t > 0.f ? t : 0.f;
            }
            float* ho = g_h0 + (size_t)m * HID + n0;
            *(float4*)(ho)     = make_float4(v[0], v[1], v[2], v[3]);
            *(float4*)(ho + 4) = make_float4(v[4], v[5], v[6], v[7]);
            int c = ei[E_EDGES + m];                 // col[m]
            float* ao = g_aA + (size_t)c * HID + n0;
            red_add_v4(ao,     v[0], v[1], v[2], v[3]);
            red_add_v4(ao + 4, v[4], v[5], v[6], v[7]);
        }
    }
}

// ---------------------------------------------------------------------------
// Conv layer (fused): h_out[e] = relu((a_in[row[e]] - h_in[e^1]) @ W + b + h0[e])
//                     a_out[col[e]] += h_out[e]
// M = E_EDGES, K = 512, N = 512.
// ---------------------------------------------------------------------------
__global__ __launch_bounds__(256, 2)
void conv_kernel(const float* __restrict__ h_in, const float* __restrict__ a_in,
                 float* __restrict__ h_out, float* __restrict__ a_out,
                 const float* __restrict__ W, const float* __restrict__ bias,
                 const int* __restrict__ ei)
{
    __shared__ float As[8][132];
    __shared__ float Bs[8][128];
    const int tid = threadIdx.x;
    const int tx = tid & 15, ty = tid >> 4;
    const int bm = blockIdx.y * 128;
    const int bn = blockIdx.x * 128;

    const int arow = tid >> 1;
    const int ac4  = (tid & 1) * 4;
    const int am   = bm + arow;
    const bool aValid = (am < E_EDGES);
    const int r = aValid ? ei[am] : 0;               // row[am]
    const float* a_src = a_in + (size_t)r * HID + ac4;
    const float* h_src = h_in + (size_t)(am ^ 1) * HID + ac4;

    const int brow = tid >> 5;
    const int bc4  = (tid & 31) * 4;
    const float* w_src = W + (size_t)brow * HID + bn + bc4;

    float acc[8][8];
    #pragma unroll
    for (int i = 0; i < 8; i++)
        #pragma unroll
        for (int j = 0; j < 8; j++) acc[i][j] = 0.f;

    for (int k0 = 0; k0 < HID; k0 += 8) {
        float4 av = make_float4(0.f, 0.f, 0.f, 0.f);
        if (aValid) {
            float4 aa = *(const float4*)(a_src + k0);
            float4 hh = *(const float4*)(h_src + k0);
            av.x = aa.x - hh.x; av.y = aa.y - hh.y;
            av.z = aa.z - hh.z; av.w = aa.w - hh.w;
        }
        As[ac4 + 0][arow] = av.x;
        As[ac4 + 1][arow] = av.y;
        As[ac4 + 2][arow] = av.z;
        As[ac4 + 3][arow] = av.w;
        *(float4*)&Bs[brow][bc4] = *(const float4*)(w_src + (size_t)k0 * HID);
        __syncthreads();

        #pragma unroll
        for (int kk = 0; kk < 8; kk++) {
            float ar[8], br[8];
            #pragma unroll
            for (int i = 0; i < 8; i++) ar[i] = As[kk][ty * 8 + i];
            #pragma unroll
            for (int j = 0; j < 8; j++) br[j] = Bs[kk][tx * 8 + j];
            #pragma unroll
            for (int i = 0; i < 8; i++)
                #pragma unroll
                for (int j = 0; j < 8; j++) acc[i][j] += ar[i] * br[j];
        }
        __syncthreads();
    }

    const int n0 = bn + tx * 8;
    float bres[8];
    #pragma unroll
    for (int j = 0; j < 8; j++) bres[j] = bias[n0 + j];

    #pragma unroll
    for (int i = 0; i < 8; i++) {
        int m = bm + ty * 8 + i;
        if (m < E_EDGES) {
            const float* h0r = g_h0 + (size_t)m * HID + n0;
            float4 r0 = *(const float4*)(h0r);
            float4 r1 = *(const float4*)(h0r + 4);
            float v[8];
            v[0] = acc[i][0] + bres[0] + r0.x; v[1] = acc[i][1] + bres[1] + r0.y;
            v[2] = acc[i][2] + bres[2] + r0.z; v[3] = acc[i][3] + bres[3] + r0.w;
            v[4] = acc[i][4] + bres[4] + r1.x; v[5] = acc[i][5] + bres[5] + r1.y;
            v[6] = acc[i][6] + bres[6] + r1.z; v[7] = acc[i][7] + bres[7] + r1.w;
            #pragma unroll
            for (int j = 0; j < 8; j++) v[j] = v[j] > 0.f ? v[j] : 0.f;
            float* ho = h_out + (size_t)m * HID + n0;
            *(float4*)(ho)     = make_float4(v[0], v[1], v[2], v[3]);
            *(float4*)(ho + 4) = make_float4(v[4], v[5], v[6], v[7]);
            int c = ei[E_EDGES + m];                 // col[m]
            float* ao = a_out + (size_t)c * HID + n0;
            red_add_v4(ao,     v[0], v[1], v[2], v[3]);
            red_add_v4(ao + 4, v[4], v[5], v[6], v[7]);
        }
    }
}

// ---------------------------------------------------------------------------
// Edge-to-node: hn[n] = relu([x[n], s[n]] @ W_e2n + b); pool[batch[n]] += hn[n]
// M = N_NODES, K = 645 (padded 648), N = 512.  batch is int32 [N].
// ---------------------------------------------------------------------------
__global__ __launch_bounds__(256, 2)
void e2n_kernel(const float* __restrict__ x, const float* __restrict__ s,
                const float* __restrict__ W, const float* __restrict__ bias,
                const int* __restrict__ bat)
{
    __shared__ float As[8][132];
    __shared__ float Bs[8][128];
    const int tid = threadIdx.x;
    const int tx = tid & 15, ty = tid >> 4;
    const int bm = blockIdx.y * 128;
    const int bn = blockIdx.x * 128;

    const int arow = tid >> 1;
    const int ac4  = (tid & 1) * 4;
    const int am   = bm + arow;
    const bool aValid = (am < N_NODES);

    const int brow = tid >> 5;
    const int bc4  = (tid & 31) * 4;

    float acc[8][8];
    #pragma unroll
    for (int i = 0; i < 8; i++)
        #pragma unroll
        for (int j = 0; j < 8; j++) acc[i][j] = 0.f;

    for (int k0 = 0; k0 < 648; k0 += 8) {
        #pragma unroll
        for (int i = 0; i < 4; i++) {
            int k = k0 + ac4 + i;
            float v = 0.f;
            if (aValid && k < KE2N) {
                v = (k < FN) ? x[(size_t)am * FN + k]
                             : s[(size_t)am * HID + (k - FN)];
            }
            As[ac4 + i][arow] = v;
        }
        int kRow = k0 + brow;
        float4 bv = make_float4(0.f, 0.f, 0.f, 0.f);
        if (kRow < KE2N) bv = *(const float4*)(W + (size_t)kRow * HID + bn + bc4);
        *(float4*)&Bs[brow][bc4] = bv;
        __syncthreads();

        #pragma unroll
        for (int kk = 0; kk < 8; kk++) {
            float ar[8], br[8];
            #pragma unroll
            for (int i = 0; i < 8; i++) ar[i] = As[kk][ty * 8 + i];
            #pragma unroll
            for (int j = 0; j < 8; j++) br[j] = Bs[kk][tx * 8 + j];
            #pragma unroll
            for (int i = 0; i < 8; i++)
                #pragma unroll
                for (int j = 0; j < 8; j++) acc[i][j] += ar[i] * br[j];
        }
        __syncthreads();
    }

    const int n0 = bn + tx * 8;
    float bres[8];
    #pragma unroll
    for (int j = 0; j < 8; j++) bres[j] = bias[n0 + j];

    #pragma unroll
    for (int i = 0; i < 8; i++) {
        int m = bm + ty * 8 + i;
        if (m < N_NODES) {
            float v[8];
            #pragma unroll
            for (int j = 0; j < 8; j++) {
                float t = acc[i][j] + bres[j];
                v[j] = t > 0.f ? t : 0.f;
            }
            int g = bat[m];                          // batch[m] (int32)
            float* po = g_pool + (size_t)g * HID + n0;
            red_add_v4(po,     v[0], v[1], v[2], v[3]);
            red_add_v4(po + 4, v[4], v[5], v[6], v[7]);
        }
    }
}

// ---------------------------------------------------------------------------
// FFN head: out[g] = relu(pool[g] @ W1 + b1) @ W2 + b2
// ---------------------------------------------------------------------------
__global__ __launch_bounds__(256)
void ffn_kernel(const float* __restrict__ W1, const float* __restrict__ b1,
                const float* __restrict__ W2, const float* __restrict__ b2,
                float* __restrict__ out)
{
    __shared__ float P[8][512];
    __shared__ float R[8 * 256];
    const int tid = threadIdx.x;
    const int g0 = blockIdx.x * 8;

    for (int i = tid; i < 8 * 512; i += 256) {
        int t = i >> 9, k = i & 511;
        P[t][k] = g_pool[(size_t)(g0 + t) * HID + k];
    }
    __syncthreads();

    float partial[8];
    #pragma unroll
    for (int t = 0; t < 8; t++) partial[t] = 0.f;

    #pragma unroll
    for (int rep = 0; rep < 2; rep++) {
        const int j = tid + rep * 256;
        float acc[8];
        #pragma unroll
        for (int t = 0; t < 8; t++) acc[t] = 0.f;
        const float bb = b1[j];
        const float w2 = W2[j];
        for (int k = 0; k < 512; k++) {
            float w = W1[(size_t)k * 512 + j];
            #pragma unroll
            for (int t = 0; t < 8; t++) acc[t] += P[t][k] * w;
        }
        #pragma unroll
        for (int t = 0; t < 8; t++) {
            float h = acc[t] + bb;
            h = h > 0.f ? h : 0.f;
            partial[t] += h * w2;
        }
    }

    #pragma unroll
    for (int t = 0; t < 8; t++) R[t * 256 + tid] = partial[t];
    __syncthreads();
    for (int srd = 128; srd > 0; srd >>= 1) {
        if (tid < srd) {
            #pragma unroll
            for (int t = 0; t < 8; t++) R[t * 256 + tid] += R[t * 256 + tid + srd];
        }
        __syncthreads();
    }
    if (tid < 8) out[g0 + tid] = R[tid * 256] + b2[0];
}

// ---------------------------------------------------------------------------
// Launch. Inputs identified by element count (robust to metadata ordering).
// ---------------------------------------------------------------------------
static int find_size(const int* s, int n, int want, int occ) {
    int c = 0;
    for (int i = 0; i < n; i++)
        if (s[i] == want) { if (c == occ) return i; c++; }
    return 0;
}

extern "C" void kernel_launch(void* const* d_in, const int* in_sizes, int n_in,
                              void* d_out, int out_size)
{
    // Unique sizes
    const int ix    = find_size(in_sizes, n_in, 3325000, 0);   // x  [25000,133]
    const int iei   = find_size(in_sizes, n_in, 200000, 0);    // edge_index [2,100000] int32
    const int iea   = find_size(in_sizes, n_in, 1400000, 0);   // edge_attr [100000,14]
    const int ibat  = find_size(in_sizes, n_in, 25000, 0);     // batch [25000] int32
    const int iWei  = find_size(in_sizes, n_in, 75264, 0);     // W_edge_init [147,512]
    const int iWcv  = find_size(in_sizes, n_in, 1048576, 0);   // W_conv [4,512,512]
    const int ibcv  = find_size(in_sizes, n_in, 2048, 0);      // b_conv [4,512]
    const int iWe2n = find_size(in_sizes, n_in, 330240, 0);    // W_e2n [645,512]
    const int iWf1  = find_size(in_sizes, n_in, 262144, 0);    // W_ffn1 [512,512]
    const int ibf2  = find_size(in_sizes, n_in, 1, 0);         // b_ffn2 [1]
    // Four 512-element entries: role depends on metadata ordering mode.
    int o512[4];
    for (int k = 0; k < 4; k++) o512[k] = find_size(in_sizes, n_in, 512, k);
    int ibei, ibe2n, ibf1, iWf2;
    if (in_sizes[0] == 3325000) {            // dict order (x first)
        ibei = o512[0]; ibe2n = o512[1]; ibf1 = o512[2]; iWf2 = o512[3];
    } else if (in_sizes[0] == 1048576) {     // ASCII alpha (W_conv first)
        iWf2 = o512[0]; ibe2n = o512[1]; ibei = o512[2]; ibf1 = o512[3];
    } else if (in_sizes[0] == 2048) {        // case-insensitive alpha (b_conv first)
        ibe2n = o512[0]; ibei = o512[1]; ibf1 = o512[2]; iWf2 = o512[3];
    } else {                                 // fallback: dict order
        ibei = o512[0]; ibe2n = o512[1]; ibf1 = o512[2]; iWf2 = o512[3];
    }

    const float* x     = (const float*)d_in[ix];
    const int*   ei    = (const int*)d_in[iei];
    const float* ea    = (const float*)d_in[iea];
    const int*   bat   = (const int*)d_in[ibat];
    const float* W_ei  = (const float*)d_in[iWei];
    const float* b_ei  = (const float*)d_in[ibei];
    const float* W_cv  = (const float*)d_in[iWcv];
    const float* b_cv  = (const float*)d_in[ibcv];
    const float* W_e2n = (const float*)d_in[iWe2n];
    const float* b_e2n = (const float*)d_in[ibe2n];
    const float* W_f1  = (const float*)d_in[iWf1];
    const float* b_f1  = (const float*)d_in[ibf1];
    const float* W_f2  = (const float*)d_in[iWf2];
    const float* b_f2  = (const float*)d_in[ibf2];
    float* out = (float*)d_out;

    float *h0, *hA, *hB, *aA, *aB, *pool;
    cudaGetSymbolAddress((void**)&h0,   g_h0);
    cudaGetSymbolAddress((void**)&hA,   g_hA);
    cudaGetSymbolAddress((void**)&hB,   g_hB);
    cudaGetSymbolAddress((void**)&aA,   g_aA);
    cudaGetSymbolAddress((void**)&aB,   g_aB);
    cudaGetSymbolAddress((void**)&pool, g_pool);

    const int a_n4 = (N_NODES * HID) / 4;
    const int p_n4 = (NG * HID) / 4;
    dim3 gE(HID / 128, (E_EDGES + 127) / 128);   // (4, 782)
    dim3 gN(HID / 128, (N_NODES + 127) / 128);   // (4, 196)

    zero_kernel<<<(a_n4 + 255) / 256, 256>>>((float4*)aA, a_n4);
    zero_kernel<<<(p_n4 + 255) / 256, 256>>>((float4*)pool, p_n4);

    // h0 + a0 = segsum(h0, col)
    edge_init_kernel<<<gE, 256>>>(x, ea, W_ei, b_ei, ei);

    // layer 0: h0 -> hA ; aA -> aB
    zero_kernel<<<(a_n4 + 255) / 256, 256>>>((float4*)aB, a_n4);
    conv_kernel<<<gE, 256>>>(h0, aA, hA, aB, W_cv + 0 * HID * HID, b_cv + 0 * HID, ei);
    // layer 1: hA -> hB ; aB -> aA
    zero_kernel<<<(a_n4 + 255) / 256, 256>>>((float4*)aA, a_n4);
    conv_kernel<<<gE, 256>>>(hA, aB, hB, aA, W_cv + 1 * HID * HID, b_cv + 1 * HID, ei);
    // layer 2: hB -> hA ; aA -> aB
    zero_kernel<<<(a_n4 + 255) / 256, 256>>>((float4*)aB, a_n4);
    conv_kernel<<<gE, 256>>>(hB, aA, hA, aB, W_cv + 2 * HID * HID, b_cv + 2 * HID, ei);
    // layer 3: hA -> hB ; aB -> aA   (aA ends as s = segsum(h4, col))
    zero_kernel<<<(a_n4 + 255) / 256, 256>>>((float4*)aA, a_n4);
    conv_kernel<<<gE, 256>>>(hA, aB, hB, aA, W_cv + 3 * HID * HID, b_cv + 3 * HID, ei);

    // node transform + pooling
    e2n_kernel<<<gN, 256>>>(x, aA, W_e2n, b_e2n, bat);

    // FFN head
    ffn_kernel<<<NG / 8, 256>>>(W_f1, b_f1, W_f2, b_f2, out);

    (void)out_size;
}